// round 5
// baseline (speedup 1.0000x reference)
#include <cuda_runtime.h>
#include <cstdint>
#include <math.h>

#define N_IMG   4
#define N_ANCH  76725
#define N_CLS   80
#define PRE     512
#define CAND_MAX 2048
#define MAXPC   100
#define MAXD    100

// logit(0.91): s > 0.91 <=> x > 2.3136168
#define XTHR 2.3136168f

// k_select smem: region0 32KB (hist 8192 u32 | keys 2048 u64), sufp@32768, wsum@34824, wsuf@34888, scal@34952
#define SEL_SMEM 35072
// k_nms2 smem: sxy@0 8K, sxyw@8192 8K, ssc@16384 2K, sar@18432 2K, mask@20480 32K, scal@53248
#define NMS2_SMEM 53312
// k_merge smem: region0 16KB (hist 4096 | keys 1024 u64), sufp@16384, wsum@18440, wsuf@18504, scal@18568
#define MRG_SMEM 18688

// ---------------- scratch ----------------
__device__ float4 g_boxes[(size_t)N_IMG * N_ANCH];
__device__ unsigned long long g_cand[(size_t)N_IMG * N_CLS * CAND_MAX];
__device__ uint32_t g_cnt[N_IMG * N_CLS];
__device__ float  g_ts[N_IMG * N_CLS * PRE];     // sorted top-512 scores
__device__ float4 g_tb[N_IMG * N_CLS * PRE];     // xywh
__device__ float4 g_te[N_IMG * N_CLS * PRE];     // xyxy
__device__ float  g_cls_scores[N_IMG * N_CLS * MAXPC];
__device__ float4 g_cls_boxes [N_IMG * N_CLS * MAXPC];

__global__ void k_zero() {
    int i = blockIdx.x * blockDim.x + threadIdx.x;
    if (i < N_IMG * N_CLS) g_cnt[i] = 0;
}

// ---------------- kernel 1: streaming candidate select + box decode ----------------
__global__ __launch_bounds__(256) void k_prep(const float* __restrict__ pred) {
    const int TOTV = N_IMG * N_ANCH * 21;
    int g = blockIdx.x * 256 + threadIdx.x;
    if (g >= TOTV) return;
    float4 v = ((const float4*)pred)[g];

    int img = g / (N_ANCH * 21);
    int rem = g - img * (N_ANCH * 21);
    int a   = rem / 21;
    int q   = rem - a * 21;

    if (q == 0) {
        int off, fw, stride;
        if      (a < 57600) { off = 0;     fw = 80; stride = 8;   }
        else if (a < 72000) { off = 57600; fw = 40; stride = 16;  }
        else if (a < 75600) { off = 72000; fw = 20; stride = 32;  }
        else if (a < 76500) { off = 75600; fw = 10; stride = 64;  }
        else                { off = 76500; fw = 5;  stride = 128; }
        int rem2 = a - off;
        int cell = rem2 / 9, k = rem2 - cell * 9;
        int iy = cell / fw, ix = cell - iy * fw;
        float sf    = (float)stride;
        float area  = 16.0f * sf * sf;
        float ratio = (k < 3) ? 0.5f : ((k < 6) ? 1.0f : 2.0f);
        int   si    = k % 3;
        float scale = (si == 0) ? 1.0f : ((si == 1) ? 1.2599210498948732f : 1.5874010519681994f);
        float hh = sqrtf(area / ratio);
        float ww = area / hh;
        float cx = (ix + 0.5f) * sf;
        float cy = (iy + 0.5f) * sf;
        float aw = scale * ww, ah = scale * hh;
        float4 b;
        b.x = v.x * 0.1f * aw + cx;
        b.y = v.y * 0.1f * ah + cy;
        b.z = __expf(v.z * 0.2f) * aw;
        b.w = __expf(v.w * 0.2f) * ah;
        g_boxes[(size_t)img * N_ANCH + a] = b;
    } else {
        float xs[4] = {v.x, v.y, v.z, v.w};
        #pragma unroll
        for (int j = 0; j < 4; j++) {
            float x = xs[j];
            if (x > XTHR) {
                int cls = 4 * q + j - 4;
                float s = __fdividef(1.0f, 1.0f + __expf(-x));
                uint32_t mono = __float_as_uint(s) | 0x80000000u;
                int list = img * N_CLS + cls;
                uint32_t idx = atomicAdd(&g_cnt[list], 1u);
                if (idx < CAND_MAX)
                    g_cand[(size_t)list * CAND_MAX + idx] =
                        ((unsigned long long)mono << 32) | (uint32_t)(~(uint32_t)a);
            }
        }
    }
}

// suffix scan of 512 per-thread sums -> sufp[tid]; sufp[512]=0
__device__ __forceinline__ void suffix_scan_512(uint32_t v, uint32_t* sufp,
                                                uint32_t* wsum, uint32_t* wsuf, int tid) {
    int lane = tid & 31, wid = tid >> 5;
    uint32_t incl = v;
    #pragma unroll
    for (int d = 1; d < 32; d <<= 1) {
        uint32_t n = __shfl_down_sync(0xFFFFFFFFu, incl, d);
        if (lane + d < 32) incl += n;
    }
    if (lane == 0) wsum[wid] = incl;
    __syncthreads();
    if (tid < 16) {
        uint32_t x = wsum[tid];
        #pragma unroll
        for (int d = 1; d < 16; d <<= 1) {
            uint32_t n = __shfl_down_sync(0x0000FFFFu, x, d);
            if (tid + d < 16) x += n;
        }
        wsuf[tid] = x;
    }
    __syncthreads();
    uint32_t below = (wid < 15) ? wsuf[wid + 1] : 0u;
    sufp[tid] = incl + below;
    if (tid == 0) sufp[512] = 0;
    __syncthreads();
}

// warp-aggregated histogram increment
__device__ __forceinline__ void agg_hist_add(uint32_t* hist, uint32_t bin, bool active) {
    uint32_t amask = __ballot_sync(0xFFFFFFFFu, active);
    if (!active) return;
    uint32_t peers  = __match_any_sync(amask, bin);
    int      leader = __ffs(peers) - 1;
    if ((threadIdx.x & 31) == leader) atomicAdd(&hist[bin], (uint32_t)__popc(peers));
}

// ---------------- kernel 2a: per (img,class) top-512 select + sort ----------------
__global__ __launch_bounds__(512) void k_select(const float* __restrict__ pred) {
    extern __shared__ char smem[];
    uint32_t* hist = (uint32_t*)smem;                       // 8192 bins (fallback only)
    unsigned long long* keys = (unsigned long long*)smem;   // 2048 keys
    uint32_t* sufp = (uint32_t*)(smem + 32768);
    uint32_t* wsum = (uint32_t*)(smem + 34824);
    uint32_t* wsuf = (uint32_t*)(smem + 34888);
    uint32_t* scal = (uint32_t*)(smem + 34952);

    int tid = threadIdx.x;
    int bid = blockIdx.x;
    int img = bid / N_CLS;
    int cls = bid - img * N_CLS;

    uint32_t cnt = g_cnt[bid];
    int SORTN;

    if (cnt >= PRE && cnt <= CAND_MAX) {
        SORTN = (cnt <= 1024) ? 1024 : CAND_MAX;
        const unsigned long long* src = &g_cand[(size_t)bid * CAND_MAX];
        for (int i = tid; i < SORTN; i += 512)
            keys[i] = (i < (int)cnt) ? src[i] : 0ull;
        __syncthreads();
    } else {
        // exact fallback: 8192-bin histogram select over full column (bits [31:19])
        SORTN = CAND_MAX;
        for (int i = tid; i < 8192; i += 512) hist[i] = 0;
        __syncthreads();
        for (int a = tid; a < N_ANCH; a += 512) {
            float x = pred[((size_t)img * N_ANCH + a) * 84 + 4 + cls];
            float s = __fdividef(1.0f, 1.0f + __expf(-x));
            uint32_t m = __float_as_uint(s) | 0x80000000u;
            agg_hist_add(hist, m >> 19, true);
        }
        __syncthreads();
        uint32_t v = 0;
        #pragma unroll
        for (int b = 0; b < 16; b++) v += hist[tid * 16 + ((b + tid) & 15)];
        suffix_scan_512(v, sufp, wsum, wsuf, tid);
        {
            uint32_t cur = sufp[tid], nxt = sufp[tid + 1];
            if (cur >= PRE && nxt < PRE) {
                uint32_t run = nxt;
                int T = tid * 16;
                for (int b = 15; b >= 0; b--) {
                    run += hist[tid * 16 + b];
                    if (run >= PRE) { T = tid * 16 + b; break; }
                }
                scal[0] = (uint32_t)T << 19;
            }
            if (tid == 0) scal[3] = 0;
        }
        __syncthreads();
        uint32_t thr = scal[0];
        __syncthreads();   // hist region about to be overwritten by keys
        for (int i = tid; i < CAND_MAX; i += 512) keys[i] = 0ull;
        __syncthreads();
        for (int a = tid; a < N_ANCH; a += 512) {
            float x = pred[((size_t)img * N_ANCH + a) * 84 + 4 + cls];
            float s = __fdividef(1.0f, 1.0f + __expf(-x));
            uint32_t m = __float_as_uint(s) | 0x80000000u;
            if (m >= thr) {
                uint32_t p = atomicAdd(&scal[3], 1u);
                if (p < CAND_MAX)
                    keys[p] = ((unsigned long long)m << 32) | (uint32_t)(~(uint32_t)a);
            }
        }
        __syncthreads();
    }

    // bitonic sort ascending; top-512 = tail
    for (int k = 2; k <= SORTN; k <<= 1) {
        for (int j = k >> 1; j > 0; j >>= 1) {
            for (int i = tid; i < SORTN; i += 512) {
                int l = i ^ j;
                if (l > i) {
                    unsigned long long x = keys[i], y = keys[l];
                    bool up = ((i & k) == 0);
                    if (up ? (x > y) : (x < y)) { keys[i] = y; keys[l] = x; }
                }
            }
            __syncthreads();
        }
    }

    // emit rank tid
    {
        unsigned long long key = keys[SORTN - 1 - tid];
        uint32_t a = ~((uint32_t)key);
        uint32_t m = (uint32_t)(key >> 32);
        float s = __uint_as_float(m ^ 0x80000000u);
        float4 b = g_boxes[(size_t)img * N_ANCH + a];
        float4 e;
        e.x = b.x - b.z * 0.5f; e.y = b.y - b.w * 0.5f;
        e.z = b.x + b.z * 0.5f; e.w = b.y + b.w * 0.5f;
        int o = bid * PRE + tid;
        g_ts[o] = s;
        g_tb[o] = b;
        g_te[o] = e;
    }
}

// ---------------- kernel 2b: IoU matrix + greedy NMS + per-class emit ----------------
__global__ __launch_bounds__(512) void k_nms2() {
    extern __shared__ char smem[];
    float4*   sxy  = (float4*)smem;
    float4*   sxyw = (float4*)(smem + 8192);
    float*    ssc  = (float*) (smem + 16384);
    float*    sar  = (float*) (smem + 18432);
    uint32_t* mask = (uint32_t*)(smem + 20480);
    uint32_t* scal = (uint32_t*)(smem + 53248);

    int tid = threadIdx.x;
    int bid = blockIdx.x;
    int o = bid * PRE + tid;

    {
        float  s = g_ts[o];
        float4 b = g_tb[o];
        float4 e = g_te[o];
        ssc[tid]  = s;
        sxyw[tid] = b;
        sxy[tid]  = e;
        sar[tid]  = (e.z - e.x) * (e.w - e.y);
    }
    __syncthreads();

    // upper-triangular IoU>0.5 bitmask
    {
        float4 me = sxy[tid];
        float  aj = sar[tid];
        int imax = (tid | 31);
        for (int i = 0; i <= imax; i++) {
            float4 bi = sxy[i];
            float lx = fmaxf(bi.x, me.x), ly = fmaxf(bi.y, me.y);
            float rx = fminf(bi.z, me.z), ry = fminf(bi.w, me.w);
            float w = fmaxf(rx - lx, 0.0f), h = fmaxf(ry - ly, 0.0f);
            float inter = w * h;
            float un = fmaxf(sar[i] + aj - inter, 1e-8f);
            bool bit = (inter > 0.5f * un) && (tid > i);
            uint32_t bm = __ballot_sync(0xFFFFFFFFu, bit);
            if ((tid & 31) == 0) mask[i * 16 + (tid >> 5)] = bm;
        }
    }
    __syncthreads();

    // chunked single-warp greedy NMS
    if (tid < 32) {
        const uint32_t F = 0xFFFFFFFFu;
        int l = tid;
        uint32_t validw = 0;
        if (l < 16) {
            #pragma unroll
            for (int b = 0; b < 32; b++)
                validw |= (ssc[l * 32 + b] > 0.05f) ? (1u << b) : 0u;
        }
        uint32_t keepw = 0xFFFFFFFFu;
        #pragma unroll 1
        for (int g = 0; g < 16; g++) {
            uint32_t vwg  = __shfl_sync(F, validw, g);
            uint32_t kloc = __shfl_sync(F, keepw, g);
            if (l == g) {
                #pragma unroll
                for (int B = 0; B < 4; B++) {
                    uint32_t mm[8];
                    #pragma unroll
                    for (int j = 0; j < 8; j++) mm[j] = mask[(32 * g + 8 * B + j) * 16 + g];
                    #pragma unroll
                    for (int j = 0; j < 8; j++) {
                        int b = 8 * B + j;
                        if (((kloc >> b) & 1u) && ((vwg >> b) & 1u)) kloc &= ~mm[j];
                    }
                }
            }
            uint32_t alive = __shfl_sync(F, kloc & vwg, g);
            if (l == g) keepw = kloc;
            if (l > g && l < 16) {
                uint32_t sup = 0;
                #pragma unroll
                for (int B = 0; B < 4; B++) {
                    uint32_t mm[8];
                    #pragma unroll
                    for (int j = 0; j < 8; j++) mm[j] = mask[(32 * g + 8 * B + j) * 16 + l];
                    #pragma unroll
                    for (int j = 0; j < 8; j++) if ((alive >> (8 * B + j)) & 1u) sup |= mm[j];
                }
                keepw &= ~sup;
            }
        }
        keepw &= validw;
        if (l >= 16) keepw = 0;

        uint32_t pc = __popc(keepw);
        uint32_t incl = pc;
        #pragma unroll
        for (int d = 1; d < 32; d <<= 1) {
            uint32_t n = __shfl_up_sync(F, incl, d);
            if (tid >= d) incl += n;
        }
        uint32_t offs  = incl - pc;
        uint32_t total = __shfl_sync(F, incl, 15);
        if (l < 16) {
            uint32_t slot = offs;
            uint32_t kw = keepw;
            while (kw) {
                int b = __ffs(kw) - 1;
                kw &= kw - 1;
                if (slot < MAXPC) {
                    int gi = bid * MAXPC + (int)slot;
                    int r  = l * 32 + b;
                    g_cls_scores[gi] = ssc[r];
                    g_cls_boxes[gi]  = sxyw[r];
                }
                slot++;
            }
        }
        if (tid == 0) scal[0] = total;
    }
    __syncthreads();
    uint32_t total = scal[0];
    if (tid < MAXPC && (uint32_t)tid >= total) {
        int gi = bid * MAXPC + tid;
        g_cls_scores[gi] = -1.0f;
        g_cls_boxes[gi]  = make_float4(-1.0f, -1.0f, -1.0f, -1.0f);
    }
}

// ---------------- kernel 3: per-image merge, two-level radix + small sort ----------------
__global__ __launch_bounds__(512) void k_merge(float* __restrict__ out) {
    extern __shared__ char smem[];
    uint32_t* hist = (uint32_t*)smem;                       // 4096 bins
    unsigned long long* keys = (unsigned long long*)smem;   // 1024 keys (overlay)
    uint32_t* sufp = (uint32_t*)(smem + 16384);
    uint32_t* wsum = (uint32_t*)(smem + 18440);
    uint32_t* wsuf = (uint32_t*)(smem + 18504);
    uint32_t* scal = (uint32_t*)(smem + 18568);

    int tid = threadIdx.x;
    int img = blockIdx.x;
    const int TOT = N_CLS * MAXPC;   // 8000

    // pass 1: coarse on bits [31:20]
    for (int i = tid; i < 4096; i += 512) hist[i] = 0;
    __syncthreads();
    for (int e0 = 0; e0 < TOT; e0 += 512) {
        int e = e0 + tid;
        uint32_t bin = 0; bool act = (e < TOT);
        if (act) {
            uint32_t b = __float_as_uint(g_cls_scores[img * TOT + e]);
            uint32_t m = (b & 0x80000000u) ? ~b : (b | 0x80000000u);
            bin = m >> 20;
        }
        agg_hist_add(hist, bin, act);
    }
    __syncthreads();

    uint32_t v = 0;
    #pragma unroll
    for (int b = 0; b < 8; b++) v += hist[tid * 8 + ((b + tid) & 7)];
    suffix_scan_512(v, sufp, wsum, wsuf, tid);

    {
        uint32_t cur = sufp[tid], nxt = sufp[tid + 1];
        if (cur >= MAXD && nxt < MAXD) {
            uint32_t run = nxt;
            int T = tid * 8;
            uint32_t above = nxt;
            for (int b = 7; b >= 0; b--) {
                uint32_t h = hist[tid * 8 + b];
                run += h;
                if (run >= MAXD) { T = tid * 8 + b; above = run - h; break; }
            }
            scal[5] = (uint32_t)T;
            scal[1] = above;
        }
        if (tid == 0) { scal[3] = 0; scal[4] = 0; }
    }
    __syncthreads();
    uint32_t T1    = scal[5];
    uint32_t above = scal[1];
    uint32_t need  = MAXD - above;

    // pass 2: refine within bin T1 on bits [19:8]
    for (int i = tid; i < 4096; i += 512) hist[i] = 0;
    __syncthreads();
    for (int e0 = 0; e0 < TOT; e0 += 512) {
        int e = e0 + tid;
        uint32_t bin = 0; bool act = false;
        if (e < TOT) {
            uint32_t b = __float_as_uint(g_cls_scores[img * TOT + e]);
            uint32_t m = (b & 0x80000000u) ? ~b : (b | 0x80000000u);
            if ((m >> 20) == T1) { act = true; bin = (m >> 8) & 0xFFFu; }
        }
        agg_hist_add(hist, bin, act);
    }
    __syncthreads();

    v = 0;
    #pragma unroll
    for (int b = 0; b < 8; b++) v += hist[tid * 8 + ((b + tid) & 7)];
    suffix_scan_512(v, sufp, wsum, wsuf, tid);

    {
        uint32_t cur = sufp[tid], nxt = sufp[tid + 1];
        if (cur >= need && nxt < need) {
            uint32_t run = nxt;
            int T = tid * 8;
            for (int b = 7; b >= 0; b--) {
                run += hist[tid * 8 + b];
                if (run >= need) { T = tid * 8 + b; break; }
            }
            scal[2] = (uint32_t)T;
        }
    }
    __syncthreads();
    uint32_t T2 = scal[2];
    __syncthreads();

    // compaction (keys overlays hist)
    for (int i = tid; i < 1024; i += 512) keys[i] = 0ull;
    __syncthreads();
    for (int e = tid; e < TOT; e += 512) {
        uint32_t b = __float_as_uint(g_cls_scores[img * TOT + e]);
        uint32_t m = (b & 0x80000000u) ? ~b : (b | 0x80000000u);
        uint32_t b1 = m >> 20;
        bool cand = (b1 > T1) || (b1 == T1 && ((m >> 8) & 0xFFFu) >= T2);
        if (cand) {
            uint32_t p = atomicAdd(&scal[3], 1u);
            if (p < 1024)
                keys[p] = ((unsigned long long)m << 32) | (uint32_t)(~(uint32_t)e);
        }
    }
    __syncthreads();
    uint32_t C = min(scal[3], 1024u);
    int SORTN = (C <= 256) ? 256 : 1024;

    for (int k = 2; k <= SORTN; k <<= 1) {
        for (int j = k >> 1; j > 0; j >>= 1) {
            for (int i = tid; i < SORTN; i += 512) {
                int l = i ^ j;
                if (l > i) {
                    unsigned long long x = keys[i], y = keys[l];
                    bool up = ((i & k) == 0);
                    if (up ? (x > y) : (x < y)) { keys[i] = y; keys[l] = x; }
                }
            }
            __syncthreads();
        }
    }

    if (tid < MAXD) {
        unsigned long long key = keys[SORTN - 1 - tid];
        uint32_t e = ~((uint32_t)key);
        float s  = g_cls_scores[img * TOT + e];
        float4 b = g_cls_boxes[img * TOT + e];
        bool valid = (s >= 0.05f);
        int cls = (int)(e / MAXPC);
        int o = img * MAXD + tid;
        float4 ob = valid ? b : make_float4(-1.0f, -1.0f, -1.0f, -1.0f);
        ((float4*)out)[o]  = ob;
        out[1600 + o] = valid ? s : -1.0f;
        out[2000 + o] = valid ? (float)cls : -1.0f;
        if (valid) atomicAdd(&scal[4], 1u);
    }
    __syncthreads();
    if (tid == 0) out[2400 + img] = (float)scal[4];
}

// ---------------- launcher ----------------
extern "C" void kernel_launch(void* const* d_in, const int* in_sizes, int n_in,
                              void* d_out, int out_size) {
    const float* pred = (const float*)d_in[1];
    if (n_in >= 1 && in_sizes[0] == N_IMG * N_ANCH * 84)
        pred = (const float*)d_in[0];

    cudaFuncSetAttribute(k_select, cudaFuncAttributeMaxDynamicSharedMemorySize, SEL_SMEM);
    cudaFuncSetAttribute(k_nms2,   cudaFuncAttributeMaxDynamicSharedMemorySize, NMS2_SMEM);
    cudaFuncSetAttribute(k_merge,  cudaFuncAttributeMaxDynamicSharedMemorySize, MRG_SMEM);

    const int TOTV = N_IMG * N_ANCH * 21;
    k_zero<<<1, 512>>>();
    k_prep<<<(TOTV + 255) / 256, 256>>>(pred);
    k_select<<<N_IMG * N_CLS, 512, SEL_SMEM>>>(pred);
    k_nms2<<<N_IMG * N_CLS, 512, NMS2_SMEM>>>();
    k_merge<<<N_IMG, 512, MRG_SMEM>>>((float*)d_out);
}